// round 14
// baseline (speedup 1.0000x reference)
#include <cuda_runtime.h>
#include <cstdint>

#define IMG_W 4096
#define IMG_H 4096
#define PX    4   // pixels per thread in x; 2 rows per thread => 8 px/thread

// Load 6 consecutive floats (cols x0-1 .. x0+4) of row yy, zero-padded in y.
__device__ __forceinline__ void load_row6(float* n, const float* __restrict__ img,
                                          int yy, int x0, bool lft, bool rgt) {
    if ((unsigned)yy >= (unsigned)IMG_H) {
#pragma unroll
        for (int i = 0; i < 6; i++) n[i] = 0.0f;
        return;
    }
    const float* p = img + (size_t)yy * IMG_W + x0;
    float4 v = __ldg(reinterpret_cast<const float4*>(p));
    n[1] = v.x; n[2] = v.y; n[3] = v.z; n[4] = v.w;
    n[0] = lft ? __ldg(p - 1) : 0.0f;
    n[5] = rgt ? __ldg(p + PX) : 0.0f;
}

// Codes for 4 pixels. Decisions bit-identical to the R9 kernel: compare
// tmp +/- di, tmp = float_bits(P) & ~7; exact ties -> first index both sides.
// ALU budget/px: 8 fused mask+attach LOP3 + 4-op VIMIN3 tree + 7-op fused
// VIADDMAX chain + ~4 decode = 23 (R9: 26).
__device__ __forceinline__ void kirsch_px4(const float n0[6], const float n1[6],
                                           const float n2[6], float code[PX],
                                           int maskReg) {
    float pt[PX + 1], pb[PX + 1], V[PX + 2];
#pragma unroll
    for (int i = 0; i < PX + 1; i++) {
        pt[i] = n0[i] + n0[i + 1];
        pb[i] = n2[i] + n2[i + 1];
    }
#pragma unroll
    for (int i = 0; i < PX + 2; i++) V[i] = n0[i] + n1[i] + n2[i];

#pragma unroll
    for (int j = 1; j <= PX; j++) {
        const float c = n0[j + 1];
        const float d = n1[j - 1];
        const float e = n1[j + 1];
        const float h = n2[j + 1];

        // Kirsch response R_k = 8*P_k - 3*T (T per-pixel const) => order by P_k.
        float P[8];
        P[0] = V[j + 1];        // c+e+h  (N)
        P[1] = pt[j] + e;       // b+c+e  (NW)
        P[2] = pt[j - 1] + c;   // a+b+c  (W)
        P[3] = pt[j - 1] + d;   // a+b+d  (SW)
        P[4] = V[j - 1];        // a+d+f  (S)
        P[5] = pb[j - 1] + d;   // d+f+g  (SE)
        P[6] = pb[j - 1] + h;   // f+g+h  (E)
        P[7] = pb[j] + e;       // e+g+h  (NE)

        // emin[di] = (bits & ~7) | di : ONE LOP3 (bits reg, mask reg, di imm).
        // Low bits clear => emin == tmp + di exactly; all P >= 0 so signed
        // int compare == float compare.
        int emin[8];
#pragma unroll
        for (int di = 0; di < 8; di++)
            emin[di] = (((int)__float_as_uint(P[di])) & maskReg) | di;

        // Min: pure 3-input tree (adds already embedded). Ties in tmp ->
        // smallest di wins (first index), matching jnp.argmin.
        int wmin = __vimin3_s32(emin[0], emin[1], emin[2]);
        int tA   = __vimin3_s32(emin[3], emin[4], emin[5]);
        int tB   = min(emin[6], emin[7]);
        wmin = __vimin3_s32(wmin, tA, tB);

        // Max: fused add+max chain; emin[di] - 2*di == tmp - di, so equal tmp
        // give strictly decreasing values in di -> first index, jnp.argmax.
        int wmax = emin[0];
        wmax = __viaddmax_s32(emin[1],  -2, wmax);
        wmax = __viaddmax_s32(emin[2],  -4, wmax);
        wmax = __viaddmax_s32(emin[3],  -6, wmax);
        wmax = __viaddmax_s32(emin[4],  -8, wmax);
        wmax = __viaddmax_s32(emin[5], -10, wmax);
        wmax = __viaddmax_s32(emin[6], -12, wmax);
        wmax = __viaddmax_s32(emin[7], -14, wmax);

        // wmax = tmp_w - w (tmp_w mult of 8) => ((-wmax)<<3)&56 == 8*am.
        // code = 8*am + an; int->float via exponent-bias FADD (fma pipe).
        const unsigned s  = (0u - (unsigned)wmax) << 3;
        const unsigned cb = (s & 56u) | 0x4B000000u | ((unsigned)wmin & 7u);
        code[j - 1] = __uint_as_float(cb) - 8388608.0f;
    }
}

// 2 output rows per thread: rows y, y+1 need input rows y-1..y+2 (4 loads).
// Natural register allocation: every __launch_bounds__ cap (R11: 32 regs,
// R13: 40 regs) made ptxas emit MORE instructions and ran slower.
__global__ __launch_bounds__(256)
void kirsch_mask_kernel(const float* __restrict__ img, float* __restrict__ out) {
    const int x0 = (blockIdx.x * blockDim.x + threadIdx.x) * PX;
    const int y  = blockIdx.y * 2;
    const bool lft = (x0 > 0);
    const bool rgt = (x0 + PX < IMG_W);

    // Runtime-opaque ~7 so the mask+attach stays ONE LOP3 per direction
    // (a compile-time mask would split into AND-imm + OR-imm).
    const int maskReg = ~((int)(blockDim.x >> 5) - 1);   // ~7 = 0xFFFFFFF8

    float r0[6], r1[6], r2[6], r3[6];
    load_row6(r0, img, y - 1, x0, lft, rgt);
    load_row6(r1, img, y,     x0, lft, rgt);
    load_row6(r2, img, y + 1, x0, lft, rgt);
    load_row6(r3, img, y + 2, x0, lft, rgt);

    float code[PX];
    kirsch_px4(r0, r1, r2, code, maskReg);
    float4* oA = reinterpret_cast<float4*>(out + (size_t)y * IMG_W + x0);
    *oA = make_float4(code[0], code[1], code[2], code[3]);

    kirsch_px4(r1, r2, r3, code, maskReg);
    float4* oB = reinterpret_cast<float4*>(out + (size_t)(y + 1) * IMG_W + x0);
    *oB = make_float4(code[0], code[1], code[2], code[3]);
}

extern "C" void kernel_launch(void* const* d_in, const int* in_sizes, int n_in,
                              void* d_out, int out_size) {
    const float* img = (const float*)d_in[0];
    for (int i = 0; i < n_in; i++) {
        if (in_sizes[i] == IMG_W * IMG_H) { img = (const float*)d_in[i]; break; }
    }
    float* out = (float*)d_out;

    dim3 block(256, 1, 1);
    dim3 grid(IMG_W / (256 * PX), IMG_H / 2, 1);  // (4, 2048)
    kirsch_mask_kernel<<<grid, block>>>(img, out);
}